// round 5
// baseline (speedup 1.0000x reference)
#include <cuda_runtime.h>
#include <cstdint>

// Problem: input [B=128, C=2, H=512, W=512] fp32.
// out[:,0] = inclusive cumsum along x (last axis, contiguous)
// out[:,1] = inclusive cumsum along y (axis -2, stride W)
//
// Single fused kernel: 8192 "x-role" blocks (warp-per-row float4 scan) +
// 256 "y-role" blocks (thread-per-column serial scan, unroll 16),
// interleaved so latency-bound y-warps and bandwidth-bound x-warps share SMs.

#define Bn 128
#define Wn 512

// grid layout: 8448 = 33 * 256 blocks. bid % 33 == 0 -> y-role (256 blocks),
// else x-role (8192 blocks).
#define GRID_BLOCKS 8448

__device__ __forceinline__ void do_scan_x(const float* __restrict__ in,
                                          float* __restrict__ out,
                                          unsigned xbid) {
    // one warp per row; 8 warps per block
    const unsigned gwarp = xbid * 8u + (threadIdx.x >> 5);   // 0..65535
    const unsigned lane  = threadIdx.x & 31u;

    const unsigned b = gwarp >> 9;     // / 512
    const unsigned y = gwarp & 511u;   // % 512

    const size_t base = ((size_t)(b * 2u + 0u) * Wn + y) * Wn;  // channel 0
    const float4* __restrict__ in4  = (const float4*)(in + base);
    float4* __restrict__       out4 = (float4*)(out + base);

    float carry = 0.0f;
#pragma unroll
    for (int it = 0; it < 4; ++it) {
        float4 v = in4[it * 32 + lane];

        float s0 = v.x;
        float s1 = s0 + v.y;
        float s2 = s1 + v.z;
        float s3 = s2 + v.w;

        float incl = s3;
#pragma unroll
        for (int off = 1; off < 32; off <<= 1) {
            float n = __shfl_up_sync(0xffffffffu, incl, off);
            if (lane >= (unsigned)off) incl += n;
        }
        float excl = incl - s3 + carry;

        float4 o;
        o.x = s0 + excl;
        o.y = s1 + excl;
        o.z = s2 + excl;
        o.w = s3 + excl;
        out4[it * 32 + lane] = o;

        carry += __shfl_sync(0xffffffffu, incl, 31);
    }
}

__device__ __forceinline__ void do_scan_y(const float* __restrict__ in,
                                          float* __restrict__ out,
                                          unsigned ybid) {
    // one thread per (image, column); 256 threads/block, 256 blocks -> 65536
    const unsigned t = ybid * 256u + threadIdx.x;
    const unsigned b = t >> 9;         // image
    const unsigned x = t & 511u;       // column

    const size_t base = ((size_t)(b * 2u + 1u) * Wn) * Wn + x;  // channel 1
    const float* __restrict__ ip = in + base;
    float* __restrict__       op = out + base;

    float acc = 0.0f;
#pragma unroll 1
    for (int y0 = 0; y0 < Wn; y0 += 16) {
        float v[16];
#pragma unroll
        for (int k = 0; k < 16; ++k)
            v[k] = ip[(size_t)(y0 + k) * Wn];
#pragma unroll
        for (int k = 0; k < 16; ++k) {
            acc += v[k];
            op[(size_t)(y0 + k) * Wn] = acc;
        }
    }
}

__global__ void __launch_bounds__(256) fused_scan_kernel(const float* __restrict__ in,
                                                         float* __restrict__ out) {
    const unsigned bid = blockIdx.x;
    const unsigned q = bid / 33u;
    if (bid == q * 33u) {
        // y-role block: index q in 0..255
        do_scan_y(in, out, q);
    } else {
        // x-role block: index = bid - (#y-blocks before it) - 1
        do_scan_x(in, out, bid - q - 1u);
    }
}

extern "C" void kernel_launch(void* const* d_in, const int* in_sizes, int n_in,
                              void* d_out, int out_size) {
    const float* in = (const float*)d_in[0];
    float* out = (float*)d_out;
    fused_scan_kernel<<<GRID_BLOCKS, 256>>>(in, out);
}